// round 4
// baseline (speedup 1.0000x reference)
#include <cuda_runtime.h>
#include <cuda_bf16.h>

// ApproxEMD: B=16, N=2048, D=3. Flash-style: never materialize NxN matrices.
// Per auction step (ef != 0):
//   colpass: S_E[m] = sum_n E, S_EC[m] = sum_n E*c[n], E = exp(ef*d(n,m))
//   small1:  s1=cost*S_E; s2=cost*S_EC/(s1+eps); wt=min(cost/(s2+eps),1);
//            g=cost*wt/(s1+eps); cost=max(cost-s2*wt,0)
//   rowpass: R[n] = sum_m E*g[m]; out += c[n]*sum_m E*g[m]*d(n,m)
//   small2:  curr = max(curr - curr*R, 0)
// Last step (ef==0): E==1 -> closed form O(N).
// Inner loops: packed f32x2 (FFMA2) with ALL packing hoisted out of the loop —
// smem holds pre-packed u64 pairs (two points per pair), -2*efl folded into
// stored coordinates. MUFU.EX2 is the designed bottleneck.

#define BB 16
#define NN 2048
#define BN (BB*NN)
#define EPSV 1e-9f
#define CH 512            // rows/cols per chunk
#define PAIRS (CH/2)      // 256
#define NCHUNK (NN/CH)    // 4

__device__ float g_cost[BN];
__device__ float g_curr[BN];
__device__ float g_g[BN];
__device__ float g_pn[BN];   // |p_n|^2
__device__ float g_lm[BN];   // |l_m|^2
__device__ float g_SEp[NCHUNK][BN];
__device__ float g_SECp[NCHUNK][BN];
__device__ float g_Rp[NCHUNK][BN];
__device__ double g_out;

typedef unsigned long long u64;

__device__ __forceinline__ float ex2f(float x) {
    float r;
    asm("ex2.approx.f32 %0, %1;" : "=f"(r) : "f"(x));
    return r;
}
__device__ __forceinline__ u64 pk(float lo, float hi) {
    u64 d;
    asm("mov.b64 %0, {%1, %2};" : "=l"(d)
        : "r"(__float_as_uint(lo)), "r"(__float_as_uint(hi)));
    return d;
}
__device__ __forceinline__ void upk(u64 v, float& lo, float& hi) {
    unsigned a, b;
    asm("mov.b64 {%0, %1}, %2;" : "=r"(a), "=r"(b) : "l"(v));
    lo = __uint_as_float(a); hi = __uint_as_float(b);
}
__device__ __forceinline__ u64 fma2(u64 a, u64 b, u64 c) {
    u64 d;
    asm("fma.rn.f32x2 %0, %1, %2, %3;" : "=l"(d) : "l"(a), "l"(b), "l"(c));
    return d;
}
__device__ __forceinline__ u64 add2(u64 a, u64 b) {
    u64 d;
    asm("add.rn.f32x2 %0, %1, %2;" : "=l"(d) : "l"(a), "l"(b));
    return d;
}
__device__ __forceinline__ u64 mul2(u64 a, u64 b) {
    u64 d;
    asm("mul.rn.f32x2 %0, %1, %2;" : "=l"(d) : "l"(a), "l"(b));
    return d;
}

__global__ void k_init(const float* __restrict__ preds,
                       const float* __restrict__ labels) {
    int idx = blockIdx.x * 256 + threadIdx.x;
    if (idx >= BN) return;
    const float* p = preds + (size_t)idx * 3;
    const float* l = labels + (size_t)idx * 3;
    g_pn[idx] = p[0]*p[0] + p[1]*p[1] + p[2]*p[2];
    g_lm[idx] = l[0]*l[0] + l[1]*l[1] + l[2]*l[2];
    g_cost[idx] = 1.0f;
    g_curr[idx] = 1.0f;
    if (idx == 0) g_out = 0.0;
}

// colpass: thread owns 1 column m; smem holds a 512-row chunk as packed pairs.
// grid (NCHUNK, 8, BB), block 256.
__global__ void __launch_bounds__(256) k_colpass(
    const float* __restrict__ preds, const float* __restrict__ labels,
    float efl /* ef*log2e */) {
    const int b = blockIdx.z;
    const int chunk = blockIdx.x;
    const int m = blockIdx.y * 256 + threadIdx.x;
    __shared__ ulonglong2 sA[PAIRS];  // (px2', py2')   p' = -2*efl*p
    __shared__ ulonglong2 sB[PAIRS];  // (pz2', wn2)    wn = efl*|p|^2
    __shared__ u64        sC[PAIRS];  // packed currency pair

    {
        const int i = threadIdx.x;           // PAIRS == 256 == blockDim
        const int n0 = b * NN + chunk * CH + 2 * i;
        const float* p = preds + (size_t)n0 * 3;
        const float m2 = -2.0f * efl;
        sA[i] = make_ulonglong2(pk(m2 * p[0], m2 * p[3]),
                                pk(m2 * p[1], m2 * p[4]));
        sB[i] = make_ulonglong2(pk(m2 * p[2], m2 * p[5]),
                                pk(efl * g_pn[n0], efl * g_pn[n0 + 1]));
        sC[i] = pk(g_curr[n0], g_curr[n0 + 1]);
    }
    __syncthreads();

    const int mi = b * NN + m;
    const float* l = labels + (size_t)mi * 3;
    const u64 lxb = pk(l[0], l[0]);
    const u64 lyb = pk(l[1], l[1]);
    const u64 lzb = pk(l[2], l[2]);
    const float wb = efl * g_lm[mi];
    const u64 wbb = pk(wb, wb);

    u64 sE = 0ull, sEC = 0ull;
#pragma unroll 4
    for (int i = 0; i < PAIRS; i++) {
        ulonglong2 A = sA[i];
        ulonglong2 Bv = sB[i];
        u64 cc = sC[i];
        u64 arg = add2(Bv.y, wbb);          // wn + wb
        arg = fma2(A.x, lxb, arg);
        arg = fma2(A.y, lyb, arg);
        arg = fma2(Bv.x, lzb, arg);         // = efl*d for both elements
        float a0, a1; upk(arg, a0, a1);
        u64 e = pk(ex2f(a0), ex2f(a1));
        sE = add2(sE, e);
        sEC = fma2(e, cc, sEC);
    }
    float e0, e1, c0, c1;
    upk(sE, e0, e1); upk(sEC, c0, c1);
    g_SEp [chunk][mi] = e0 + e1;
    g_SECp[chunk][mi] = c0 + c1;
}

__global__ void k_small1() {
    int idx = blockIdx.x * 256 + threadIdx.x;
    if (idx >= BN) return;
    float se = 0.0f, sec = 0.0f;
#pragma unroll
    for (int ch = 0; ch < NCHUNK; ch++) {
        se += g_SEp[ch][idx];
        sec += g_SECp[ch][idx];
    }
    float cost = g_cost[idx];
    float s1 = cost * se;
    float s2 = cost * sec / (s1 + EPSV);
    float wt = fminf(cost / (s2 + EPSV), 1.0f);
    g_g[idx] = cost * wt / (s1 + EPSV);
    g_cost[idx] = fmaxf(cost - s2 * wt, 0.0f);
}

// rowpass: thread owns 1 row n; smem holds a 512-col chunk as packed pairs.
// grid (NCHUNK, 8, BB), block 256.
__global__ void __launch_bounds__(256) k_rowpass(
    const float* __restrict__ preds, const float* __restrict__ labels,
    float efl, float inv_efl) {
    const int b = blockIdx.z;
    const int chunk = blockIdx.x;
    const int n = blockIdx.y * 256 + threadIdx.x;
    __shared__ ulonglong2 sA[PAIRS];  // (lx2', ly2')   l' = -2*efl*l
    __shared__ ulonglong2 sB[PAIRS];  // (lz2', wl2)    wl = efl*|l|^2
    __shared__ u64        sG[PAIRS];  // packed g pair
    __shared__ float      sred[8];

    {
        const int i = threadIdx.x;
        const int m0 = b * NN + chunk * CH + 2 * i;
        const float* l = labels + (size_t)m0 * 3;
        const float m2 = -2.0f * efl;
        sA[i] = make_ulonglong2(pk(m2 * l[0], m2 * l[3]),
                                pk(m2 * l[1], m2 * l[4]));
        sB[i] = make_ulonglong2(pk(m2 * l[2], m2 * l[5]),
                                pk(efl * g_lm[m0], efl * g_lm[m0 + 1]));
        sG[i] = pk(g_g[m0], g_g[m0 + 1]);
    }
    __syncthreads();

    const int ni = b * NN + n;
    const float* p = preds + (size_t)ni * 3;
    const u64 pxb = pk(p[0], p[0]);
    const u64 pyb = pk(p[1], p[1]);
    const u64 pzb = pk(p[2], p[2]);
    const float wp = efl * g_pn[ni];
    const u64 wpb = pk(wp, wp);

    u64 rAcc = 0ull, oAcc = 0ull;
#pragma unroll 4
    for (int i = 0; i < PAIRS; i++) {
        ulonglong2 A = sA[i];
        ulonglong2 Bv = sB[i];
        u64 g2 = sG[i];
        u64 arg = add2(Bv.y, wpb);          // wl + wp
        arg = fma2(A.x, pxb, arg);
        arg = fma2(A.y, pyb, arg);
        arg = fma2(Bv.x, pzb, arg);         // = efl*d
        float a0, a1; upk(arg, a0, a1);
        u64 e = pk(ex2f(a0), ex2f(a1));
        u64 t = mul2(e, g2);
        rAcc = add2(rAcc, t);
        oAcc = fma2(t, arg, oAcc);          // accumulates efl * sum t*d
    }
    float r0, r1, o0, o1;
    upk(rAcc, r0, r1); upk(oAcc, o0, o1);
    g_Rp[chunk][ni] = r0 + r1;

    float v = inv_efl * g_curr[ni] * (o0 + o1);
#pragma unroll
    for (int off = 16; off > 0; off >>= 1)
        v += __shfl_down_sync(0xFFFFFFFFu, v, off);
    if ((threadIdx.x & 31) == 0) sred[threadIdx.x >> 5] = v;
    __syncthreads();
    if (threadIdx.x == 0) {
        float s = 0.0f;
#pragma unroll
        for (int w = 0; w < 8; w++) s += sred[w];
        atomicAdd(&g_out, (double)s);
    }
}

__global__ void k_small2() {
    int idx = blockIdx.x * 256 + threadIdx.x;
    if (idx >= BN) return;
    float r = 0.0f;
#pragma unroll
    for (int ch = 0; ch < NCHUNK; ch++) r += g_Rp[ch][idx];
    float c = g_curr[idx];
    g_curr[idx] = fmaxf(c - c * r, 0.0f);
}

// Last step (ef==0): E==1 everywhere. Closed form, O(N) per batch.
// out += G*sum(c*pn) + C*sum(g*lm) - 2*dot(sum(c*p), sum(g*l))
__global__ void k_ef0(const float* __restrict__ preds,
                      const float* __restrict__ labels) {
    const int b = blockIdx.x;
    const int tid = threadIdx.x;
    __shared__ float red[256];

    float C = 0, CP = 0, CX = 0, CY = 0, CZ = 0;
    for (int n = tid; n < NN; n += 256) {
        float c = g_curr[b * NN + n];
        const float* p = preds + ((size_t)b * NN + n) * 3;
        C += c; CP += c * g_pn[b*NN+n];
        CX += c * p[0]; CY += c * p[1]; CZ += c * p[2];
    }
    auto reduce = [&](float v) -> float {
        red[tid] = v; __syncthreads();
        for (int s = 128; s > 0; s >>= 1) {
            if (tid < s) red[tid] += red[tid + s];
            __syncthreads();
        }
        float r = red[0]; __syncthreads();
        return r;
    };
    float Cs = reduce(C);
    float CPs = reduce(CP);
    float CXs = reduce(CX);
    float CYs = reduce(CY);
    float CZs = reduce(CZ);

    float G = 0, GL = 0, GX = 0, GY = 0, GZ = 0;
    for (int m = tid; m < NN; m += 256) {
        float cost = g_cost[b * NN + m];
        float s1 = cost * (float)NN;
        float s2 = cost * Cs / (s1 + EPSV);
        float wt = fminf(cost / (s2 + EPSV), 1.0f);
        float g = cost * wt / (s1 + EPSV);
        const float* l = labels + ((size_t)b * NN + m) * 3;
        G += g; GL += g * g_lm[b*NN+m];
        GX += g * l[0]; GY += g * l[1]; GZ += g * l[2];
    }
    float Gs = reduce(G);
    float GLs = reduce(GL);
    float GXs = reduce(GX);
    float GYs = reduce(GY);
    float GZs = reduce(GZ);

    if (tid == 0) {
        double ob = (double)CPs * Gs + (double)Cs * GLs
                  - 2.0 * ((double)CXs * GXs + (double)CYs * GYs + (double)CZs * GZs);
        atomicAdd(&g_out, ob);
    }
}

__global__ void k_write(float* out) {
    out[0] = (float)g_out;
}

extern "C" void kernel_launch(void* const* d_in, const int* in_sizes, int n_in,
                              void* d_out, int out_size) {
    const float* preds = (const float*)d_in[0];
    const float* labels = (const float*)d_in[1];
    float* out = (float*)d_out;

    static const float EF[9] = {
        -16384.0f, -4096.0f, -1024.0f, -256.0f, -64.0f,
        -16.0f, -4.0f, -1.0f, -0.25f
    };
    const float L2E = 1.4426950408889634f;

    k_init<<<BN / 256, 256>>>(preds, labels);

    dim3 grid(NCHUNK, 8, BB);
    for (int s = 0; s < 9; s++) {
        float efl = EF[s] * L2E;
        k_colpass<<<grid, 256>>>(preds, labels, efl);
        k_small1<<<BN / 256, 256>>>();
        k_rowpass<<<grid, 256>>>(preds, labels, efl, 1.0f / efl);
        k_small2<<<BN / 256, 256>>>();
    }
    k_ef0<<<BB, 256>>>(preds, labels);   // ef = 0 step, closed form
    k_write<<<1, 1>>>(out);
}

// round 5
// speedup vs baseline: 1.1033x; 1.1033x over previous
#include <cuda_runtime.h>
#include <cuda_bf16.h>

// ApproxEMD: B=16, N=2048, D=3. Flash-style: never materialize NxN matrices.
// Per auction step (ef != 0):
//   colpass: S_E[m] = sum_n E, S_EC[m] = sum_n E*c[n], E = exp(ef*d(n,m))
//   small1:  s1=cost*S_E; s2=cost*S_EC/(s1+eps); wt=min(cost/(s2+eps),1);
//            g=cost*wt/(s1+eps); cost=max(cost-s2*wt,0)
//   rowpass: R[n] = sum_m E*g[m]; out += c[n]*sum_m E*g[m]*d(n,m)
//   small2:  curr = max(curr - curr*R, 0)
// Last step (ef==0): E==1 -> closed form O(N).
// Inner loops: packed f32x2 (FFMA2); smem pre-packed u64 pairs with -2*efl
// folded in; unroll 8 + dual accumulators + 128-reg budget for ILP.

#define BB 16
#define NN 2048
#define BN (BB*NN)
#define EPSV 1e-9f
#define CH 512            // rows/cols per chunk
#define PAIRS (CH/2)      // 256
#define NCHUNK (NN/CH)    // 4

__device__ float g_cost[BN];
__device__ float g_curr[BN];
__device__ float g_g[BN];
__device__ float g_pn[BN];   // |p_n|^2
__device__ float g_lm[BN];   // |l_m|^2
__device__ float g_SEp[NCHUNK][BN];
__device__ float g_SECp[NCHUNK][BN];
__device__ float g_Rp[NCHUNK][BN];
__device__ double g_out;

typedef unsigned long long u64;

__device__ __forceinline__ float ex2f(float x) {
    float r;
    asm("ex2.approx.f32 %0, %1;" : "=f"(r) : "f"(x));
    return r;
}
__device__ __forceinline__ u64 pk(float lo, float hi) {
    u64 d;
    asm("mov.b64 %0, {%1, %2};" : "=l"(d)
        : "r"(__float_as_uint(lo)), "r"(__float_as_uint(hi)));
    return d;
}
__device__ __forceinline__ void upk(u64 v, float& lo, float& hi) {
    unsigned a, b;
    asm("mov.b64 {%0, %1}, %2;" : "=r"(a), "=r"(b) : "l"(v));
    lo = __uint_as_float(a); hi = __uint_as_float(b);
}
__device__ __forceinline__ u64 fma2(u64 a, u64 b, u64 c) {
    u64 d;
    asm("fma.rn.f32x2 %0, %1, %2, %3;" : "=l"(d) : "l"(a), "l"(b), "l"(c));
    return d;
}
__device__ __forceinline__ u64 add2(u64 a, u64 b) {
    u64 d;
    asm("add.rn.f32x2 %0, %1, %2;" : "=l"(d) : "l"(a), "l"(b));
    return d;
}
__device__ __forceinline__ u64 mul2(u64 a, u64 b) {
    u64 d;
    asm("mul.rn.f32x2 %0, %1, %2;" : "=l"(d) : "l"(a), "l"(b));
    return d;
}

__global__ void k_init(const float* __restrict__ preds,
                       const float* __restrict__ labels) {
    int idx = blockIdx.x * 256 + threadIdx.x;
    if (idx >= BN) return;
    const float* p = preds + (size_t)idx * 3;
    const float* l = labels + (size_t)idx * 3;
    g_pn[idx] = p[0]*p[0] + p[1]*p[1] + p[2]*p[2];
    g_lm[idx] = l[0]*l[0] + l[1]*l[1] + l[2]*l[2];
    g_cost[idx] = 1.0f;
    g_curr[idx] = 1.0f;
    if (idx == 0) g_out = 0.0;
}

// colpass: thread owns 1 column m; smem holds a 512-row chunk as packed pairs.
// grid (NCHUNK, 8, BB), block 256.
__global__ void __launch_bounds__(256, 2) k_colpass(
    const float* __restrict__ preds, const float* __restrict__ labels,
    float efl /* ef*log2e */) {
    const int b = blockIdx.z;
    const int chunk = blockIdx.x;
    const int m = blockIdx.y * 256 + threadIdx.x;
    __shared__ ulonglong2 sA[PAIRS];  // (px2', py2')   p' = -2*efl*p
    __shared__ ulonglong2 sB[PAIRS];  // (pz2', wn2)    wn = efl*|p|^2
    __shared__ u64        sC[PAIRS];  // packed currency pair

    {
        const int i = threadIdx.x;           // PAIRS == 256 == blockDim
        const int n0 = b * NN + chunk * CH + 2 * i;
        const float* p = preds + (size_t)n0 * 3;
        const float m2 = -2.0f * efl;
        sA[i] = make_ulonglong2(pk(m2 * p[0], m2 * p[3]),
                                pk(m2 * p[1], m2 * p[4]));
        sB[i] = make_ulonglong2(pk(m2 * p[2], m2 * p[5]),
                                pk(efl * g_pn[n0], efl * g_pn[n0 + 1]));
        sC[i] = pk(g_curr[n0], g_curr[n0 + 1]);
    }
    __syncthreads();

    const int mi = b * NN + m;
    const float* l = labels + (size_t)mi * 3;
    const u64 lxb = pk(l[0], l[0]);
    const u64 lyb = pk(l[1], l[1]);
    const u64 lzb = pk(l[2], l[2]);
    const float wb = efl * g_lm[mi];
    const u64 wbb = pk(wb, wb);

    // dual accumulator sets to decouple chains
    u64 sE0 = 0ull, sEC0 = 0ull, sE1 = 0ull, sEC1 = 0ull;
#pragma unroll 8
    for (int i = 0; i < PAIRS; i += 2) {
        {
            ulonglong2 A = sA[i];
            ulonglong2 Bv = sB[i];
            u64 cc = sC[i];
            u64 arg = add2(Bv.y, wbb);
            arg = fma2(A.x, lxb, arg);
            arg = fma2(A.y, lyb, arg);
            arg = fma2(Bv.x, lzb, arg);
            float a0, a1; upk(arg, a0, a1);
            u64 e = pk(ex2f(a0), ex2f(a1));
            sE0 = add2(sE0, e);
            sEC0 = fma2(e, cc, sEC0);
        }
        {
            ulonglong2 A = sA[i + 1];
            ulonglong2 Bv = sB[i + 1];
            u64 cc = sC[i + 1];
            u64 arg = add2(Bv.y, wbb);
            arg = fma2(A.x, lxb, arg);
            arg = fma2(A.y, lyb, arg);
            arg = fma2(Bv.x, lzb, arg);
            float a0, a1; upk(arg, a0, a1);
            u64 e = pk(ex2f(a0), ex2f(a1));
            sE1 = add2(sE1, e);
            sEC1 = fma2(e, cc, sEC1);
        }
    }
    u64 sE = add2(sE0, sE1), sEC = add2(sEC0, sEC1);
    float e0, e1, c0, c1;
    upk(sE, e0, e1); upk(sEC, c0, c1);
    g_SEp [chunk][mi] = e0 + e1;
    g_SECp[chunk][mi] = c0 + c1;
}

__global__ void k_small1() {
    int idx = blockIdx.x * 256 + threadIdx.x;
    if (idx >= BN) return;
    float se = 0.0f, sec = 0.0f;
#pragma unroll
    for (int ch = 0; ch < NCHUNK; ch++) {
        se += g_SEp[ch][idx];
        sec += g_SECp[ch][idx];
    }
    float cost = g_cost[idx];
    float s1 = cost * se;
    float s2 = cost * sec / (s1 + EPSV);
    float wt = fminf(cost / (s2 + EPSV), 1.0f);
    g_g[idx] = cost * wt / (s1 + EPSV);
    g_cost[idx] = fmaxf(cost - s2 * wt, 0.0f);
}

// rowpass: thread owns 1 row n; smem holds a 512-col chunk as packed pairs.
// grid (NCHUNK, 8, BB), block 256.
__global__ void __launch_bounds__(256, 2) k_rowpass(
    const float* __restrict__ preds, const float* __restrict__ labels,
    float efl, float inv_efl) {
    const int b = blockIdx.z;
    const int chunk = blockIdx.x;
    const int n = blockIdx.y * 256 + threadIdx.x;
    __shared__ ulonglong2 sA[PAIRS];  // (lx2', ly2')   l' = -2*efl*l
    __shared__ ulonglong2 sB[PAIRS];  // (lz2', wl2)    wl = efl*|l|^2
    __shared__ u64        sG[PAIRS];  // packed g pair
    __shared__ float      sred[8];

    {
        const int i = threadIdx.x;
        const int m0 = b * NN + chunk * CH + 2 * i;
        const float* l = labels + (size_t)m0 * 3;
        const float m2 = -2.0f * efl;
        sA[i] = make_ulonglong2(pk(m2 * l[0], m2 * l[3]),
                                pk(m2 * l[1], m2 * l[4]));
        sB[i] = make_ulonglong2(pk(m2 * l[2], m2 * l[5]),
                                pk(efl * g_lm[m0], efl * g_lm[m0 + 1]));
        sG[i] = pk(g_g[m0], g_g[m0 + 1]);
    }
    __syncthreads();

    const int ni = b * NN + n;
    const float* p = preds + (size_t)ni * 3;
    const u64 pxb = pk(p[0], p[0]);
    const u64 pyb = pk(p[1], p[1]);
    const u64 pzb = pk(p[2], p[2]);
    const float wp = efl * g_pn[ni];
    const u64 wpb = pk(wp, wp);

    u64 r0a = 0ull, o0a = 0ull, r1a = 0ull, o1a = 0ull;
#pragma unroll 8
    for (int i = 0; i < PAIRS; i += 2) {
        {
            ulonglong2 A = sA[i];
            ulonglong2 Bv = sB[i];
            u64 g2 = sG[i];
            u64 arg = add2(Bv.y, wpb);
            arg = fma2(A.x, pxb, arg);
            arg = fma2(A.y, pyb, arg);
            arg = fma2(Bv.x, pzb, arg);
            float a0, a1; upk(arg, a0, a1);
            u64 e = pk(ex2f(a0), ex2f(a1));
            u64 t = mul2(e, g2);
            r0a = add2(r0a, t);
            o0a = fma2(t, arg, o0a);    // accumulates efl * sum t*d
        }
        {
            ulonglong2 A = sA[i + 1];
            ulonglong2 Bv = sB[i + 1];
            u64 g2 = sG[i + 1];
            u64 arg = add2(Bv.y, wpb);
            arg = fma2(A.x, pxb, arg);
            arg = fma2(A.y, pyb, arg);
            arg = fma2(Bv.x, pzb, arg);
            float a0, a1; upk(arg, a0, a1);
            u64 e = pk(ex2f(a0), ex2f(a1));
            u64 t = mul2(e, g2);
            r1a = add2(r1a, t);
            o1a = fma2(t, arg, o1a);
        }
    }
    u64 rAcc = add2(r0a, r1a), oAcc = add2(o0a, o1a);
    float r0, r1, o0, o1;
    upk(rAcc, r0, r1); upk(oAcc, o0, o1);
    g_Rp[chunk][ni] = r0 + r1;

    float v = inv_efl * g_curr[ni] * (o0 + o1);
#pragma unroll
    for (int off = 16; off > 0; off >>= 1)
        v += __shfl_down_sync(0xFFFFFFFFu, v, off);
    if ((threadIdx.x & 31) == 0) sred[threadIdx.x >> 5] = v;
    __syncthreads();
    if (threadIdx.x == 0) {
        float s = 0.0f;
#pragma unroll
        for (int w = 0; w < 8; w++) s += sred[w];
        atomicAdd(&g_out, (double)s);
    }
}

__global__ void k_small2() {
    int idx = blockIdx.x * 256 + threadIdx.x;
    if (idx >= BN) return;
    float r = 0.0f;
#pragma unroll
    for (int ch = 0; ch < NCHUNK; ch++) r += g_Rp[ch][idx];
    float c = g_curr[idx];
    g_curr[idx] = fmaxf(c - c * r, 0.0f);
}

// Last step (ef==0): E==1 everywhere. Closed form, O(N) per batch.
// out += G*sum(c*pn) + C*sum(g*lm) - 2*dot(sum(c*p), sum(g*l))
__global__ void k_ef0(const float* __restrict__ preds,
                      const float* __restrict__ labels) {
    const int b = blockIdx.x;
    const int tid = threadIdx.x;
    __shared__ float red[256];

    float C = 0, CP = 0, CX = 0, CY = 0, CZ = 0;
    for (int n = tid; n < NN; n += 256) {
        float c = g_curr[b * NN + n];
        const float* p = preds + ((size_t)b * NN + n) * 3;
        C += c; CP += c * g_pn[b*NN+n];
        CX += c * p[0]; CY += c * p[1]; CZ += c * p[2];
    }
    auto reduce = [&](float v) -> float {
        red[tid] = v; __syncthreads();
        for (int s = 128; s > 0; s >>= 1) {
            if (tid < s) red[tid] += red[tid + s];
            __syncthreads();
        }
        float r = red[0]; __syncthreads();
        return r;
    };
    float Cs = reduce(C);
    float CPs = reduce(CP);
    float CXs = reduce(CX);
    float CYs = reduce(CY);
    float CZs = reduce(CZ);

    float G = 0, GL = 0, GX = 0, GY = 0, GZ = 0;
    for (int m = tid; m < NN; m += 256) {
        float cost = g_cost[b * NN + m];
        float s1 = cost * (float)NN;
        float s2 = cost * Cs / (s1 + EPSV);
        float wt = fminf(cost / (s2 + EPSV), 1.0f);
        float g = cost * wt / (s1 + EPSV);
        const float* l = labels + ((size_t)b * NN + m) * 3;
        G += g; GL += g * g_lm[b*NN+m];
        GX += g * l[0]; GY += g * l[1]; GZ += g * l[2];
    }
    float Gs = reduce(G);
    float GLs = reduce(GL);
    float GXs = reduce(GX);
    float GYs = reduce(GY);
    float GZs = reduce(GZ);

    if (tid == 0) {
        double ob = (double)CPs * Gs + (double)Cs * GLs
                  - 2.0 * ((double)CXs * GXs + (double)CYs * GYs + (double)CZs * GZs);
        atomicAdd(&g_out, ob);
    }
}

__global__ void k_write(float* out) {
    out[0] = (float)g_out;
}

extern "C" void kernel_launch(void* const* d_in, const int* in_sizes, int n_in,
                              void* d_out, int out_size) {
    const float* preds = (const float*)d_in[0];
    const float* labels = (const float*)d_in[1];
    float* out = (float*)d_out;

    static const float EF[9] = {
        -16384.0f, -4096.0f, -1024.0f, -256.0f, -64.0f,
        -16.0f, -4.0f, -1.0f, -0.25f
    };
    const float L2E = 1.4426950408889634f;

    k_init<<<BN / 256, 256>>>(preds, labels);

    dim3 grid(NCHUNK, 8, BB);
    for (int s = 0; s < 9; s++) {
        float efl = EF[s] * L2E;
        k_colpass<<<grid, 256>>>(preds, labels, efl);
        k_small1<<<BN / 256, 256>>>();
        k_rowpass<<<grid, 256>>>(preds, labels, efl, 1.0f / efl);
        k_small2<<<BN / 256, 256>>>();
    }
    k_ef0<<<BB, 256>>>(preds, labels);   // ef = 0 step, closed form
    k_write<<<1, 1>>>(out);
}

// round 6
// speedup vs baseline: 1.1925x; 1.0809x over previous
#include <cuda_runtime.h>
#include <cuda_bf16.h>

// ApproxEMD: B=16, N=2048, D=3. Flash-style: never materialize NxN matrices.
// Register-tiled passes: thread owns 4 outputs (2 f32x2 pairs); smem holds the
// opposing side broadcast-packed (pk(v,v)) so inner loop has zero packing ops.
// Warp-ballot underflow skip for large-|ef| steps: exp2(arg)==0 exactly in fp32
// when arg < -150, so skipping MUFU+accum is bit-equivalent, matching the
// fp32 reference's own underflow.

#define BB 16
#define NN 2048
#define BN (BB*NN)
#define EPSV 1e-9f
#define CH 128            // rows/cols per smem chunk
#define NCHUNK (NN/CH)    // 16

__device__ float g_cost[BN];
__device__ float g_curr[BN];
__device__ float g_g[BN];
__device__ float g_pn[BN];   // |p_n|^2
__device__ float g_lm[BN];   // |l_m|^2
__device__ float g_SEp[NCHUNK][BN];
__device__ float g_SECp[NCHUNK][BN];
__device__ float g_Rp[NCHUNK][BN];
__device__ double g_out;

typedef unsigned long long u64;

__device__ __forceinline__ float ex2f(float x) {
    float r;
    asm("ex2.approx.f32 %0, %1;" : "=f"(r) : "f"(x));
    return r;
}
__device__ __forceinline__ u64 pk(float lo, float hi) {
    u64 d;
    asm("mov.b64 %0, {%1, %2};" : "=l"(d)
        : "r"(__float_as_uint(lo)), "r"(__float_as_uint(hi)));
    return d;
}
__device__ __forceinline__ void upk(u64 v, float& lo, float& hi) {
    unsigned a, b;
    asm("mov.b64 {%0, %1}, %2;" : "=r"(a), "=r"(b) : "l"(v));
    lo = __uint_as_float(a); hi = __uint_as_float(b);
}
__device__ __forceinline__ u64 fma2(u64 a, u64 b, u64 c) {
    u64 d;
    asm("fma.rn.f32x2 %0, %1, %2, %3;" : "=l"(d) : "l"(a), "l"(b), "l"(c));
    return d;
}
__device__ __forceinline__ u64 add2(u64 a, u64 b) {
    u64 d;
    asm("add.rn.f32x2 %0, %1, %2;" : "=l"(d) : "l"(a), "l"(b));
    return d;
}
__device__ __forceinline__ u64 mul2(u64 a, u64 b) {
    u64 d;
    asm("mul.rn.f32x2 %0, %1, %2;" : "=l"(d) : "l"(a), "l"(b));
    return d;
}

#define UTH (-150.0f)   // exp2(arg)==+0.0f for arg < -150 (even via denormals)

__global__ void k_init(const float* __restrict__ preds,
                       const float* __restrict__ labels) {
    int idx = blockIdx.x * 256 + threadIdx.x;
    if (idx >= BN) return;
    const float* p = preds + (size_t)idx * 3;
    const float* l = labels + (size_t)idx * 3;
    g_pn[idx] = p[0]*p[0] + p[1]*p[1] + p[2]*p[2];
    g_lm[idx] = l[0]*l[0] + l[1]*l[1] + l[2]*l[2];
    g_cost[idx] = 1.0f;
    g_curr[idx] = 1.0f;
    if (idx == 0) g_out = 0.0;
}

// colpass: thread owns 4 columns m (2 packed pairs); smem = broadcast-packed
// 128-row chunk. grid (NCHUNK, 2, BB), block 256.
template <bool SKIP>
__global__ void __launch_bounds__(256, 2) k_colpass(
    const float* __restrict__ preds, const float* __restrict__ labels,
    float efl /* ef*log2e */) {
    const int b = blockIdx.z;
    const int chunk = blockIdx.x;
    __shared__ ulonglong2 sA[CH];  // (px2, py2)  broadcast-packed raw coords
    __shared__ ulonglong2 sB[CH];  // (pz2, wn2)  wn = efl*|p|^2
    __shared__ u64        sC[CH];  // (c, c)

    if (threadIdx.x < CH) {
        const int n = b * NN + chunk * CH + threadIdx.x;
        const float* p = preds + (size_t)n * 3;
        float wn = efl * g_pn[n];
        float c = g_curr[n];
        sA[threadIdx.x] = make_ulonglong2(pk(p[0], p[0]), pk(p[1], p[1]));
        sB[threadIdx.x] = make_ulonglong2(pk(p[2], p[2]), pk(wn, wn));
        sC[threadIdx.x] = pk(c, c);
    }
    __syncthreads();

    // owned columns: m0, m0+256 (pair A), m0+512, m0+768 (pair B)
    const int m0 = b * NN + blockIdx.y * 1024 + threadIdx.x;
    const float m2 = -2.0f * efl;
    const float* lA0 = labels + (size_t)m0 * 3;
    const float* lA1 = labels + (size_t)(m0 + 256) * 3;
    const float* lB0 = labels + (size_t)(m0 + 512) * 3;
    const float* lB1 = labels + (size_t)(m0 + 768) * 3;
    const u64 lxA = pk(m2*lA0[0], m2*lA1[0]), lyA = pk(m2*lA0[1], m2*lA1[1]);
    const u64 lzA = pk(m2*lA0[2], m2*lA1[2]);
    const u64 lxB = pk(m2*lB0[0], m2*lB1[0]), lyB = pk(m2*lB0[1], m2*lB1[1]);
    const u64 lzB = pk(m2*lB0[2], m2*lB1[2]);
    const u64 wbA = pk(efl * g_lm[m0],       efl * g_lm[m0 + 256]);
    const u64 wbB = pk(efl * g_lm[m0 + 512], efl * g_lm[m0 + 768]);

    u64 sEA = 0ull, sECA = 0ull, sEB = 0ull, sECB = 0ull;
#pragma unroll 4
    for (int i = 0; i < CH; i++) {
        ulonglong2 A = sA[i];
        ulonglong2 Bv = sB[i];
        u64 c2 = sC[i];
        u64 argA = fma2(Bv.x, lzA, fma2(A.y, lyA, fma2(A.x, lxA, add2(Bv.y, wbA))));
        u64 argB = fma2(Bv.x, lzB, fma2(A.y, lyB, fma2(A.x, lxB, add2(Bv.y, wbB))));
        float a0, a1, b0, b1;
        upk(argA, a0, a1); upk(argB, b0, b1);
        if (SKIP) {
            float mx = fmaxf(fmaxf(a0, a1), fmaxf(b0, b1));
            if (__ballot_sync(0xFFFFFFFFu, mx > UTH) == 0u) continue;
        }
        u64 eA = pk(ex2f(a0), ex2f(a1));
        u64 eB = pk(ex2f(b0), ex2f(b1));
        sEA = add2(sEA, eA); sECA = fma2(eA, c2, sECA);
        sEB = add2(sEB, eB); sECB = fma2(eB, c2, sECB);
    }
    float e0, e1, e2, e3, c0, c1, c2v, c3;
    upk(sEA, e0, e1); upk(sEB, e2, e3);
    upk(sECA, c0, c1); upk(sECB, c2v, c3);
    g_SEp [chunk][m0      ] = e0;
    g_SEp [chunk][m0 + 256] = e1;
    g_SEp [chunk][m0 + 512] = e2;
    g_SEp [chunk][m0 + 768] = e3;
    g_SECp[chunk][m0      ] = c0;
    g_SECp[chunk][m0 + 256] = c1;
    g_SECp[chunk][m0 + 512] = c2v;
    g_SECp[chunk][m0 + 768] = c3;
}

__global__ void k_small1() {
    int idx = blockIdx.x * 256 + threadIdx.x;
    if (idx >= BN) return;
    float se = 0.0f, sec = 0.0f;
#pragma unroll
    for (int ch = 0; ch < NCHUNK; ch++) {
        se += g_SEp[ch][idx];
        sec += g_SECp[ch][idx];
    }
    float cost = g_cost[idx];
    float s1 = cost * se;
    float s2 = cost * sec / (s1 + EPSV);
    float wt = fminf(cost / (s2 + EPSV), 1.0f);
    g_g[idx] = cost * wt / (s1 + EPSV);
    g_cost[idx] = fmaxf(cost - s2 * wt, 0.0f);
}

// rowpass: thread owns 4 rows n (2 packed pairs); smem = broadcast-packed
// 128-col chunk. grid (NCHUNK, 2, BB), block 256.
template <bool SKIP>
__global__ void __launch_bounds__(256, 2) k_rowpass(
    const float* __restrict__ preds, const float* __restrict__ labels,
    float efl, float inv_efl) {
    const int b = blockIdx.z;
    const int chunk = blockIdx.x;
    __shared__ ulonglong2 sA[CH];  // (lx2, ly2) broadcast-packed
    __shared__ ulonglong2 sB[CH];  // (lz2, wl2) wl = efl*|l|^2
    __shared__ u64        sG[CH];  // (g, g)
    __shared__ float      sred[8];

    if (threadIdx.x < CH) {
        const int m = b * NN + chunk * CH + threadIdx.x;
        const float* l = labels + (size_t)m * 3;
        float wl = efl * g_lm[m];
        float gv = g_g[m];
        sA[threadIdx.x] = make_ulonglong2(pk(l[0], l[0]), pk(l[1], l[1]));
        sB[threadIdx.x] = make_ulonglong2(pk(l[2], l[2]), pk(wl, wl));
        sG[threadIdx.x] = pk(gv, gv);
    }
    __syncthreads();

    const int n0 = b * NN + blockIdx.y * 1024 + threadIdx.x;
    const float m2 = -2.0f * efl;
    const float* pA0 = preds + (size_t)n0 * 3;
    const float* pA1 = preds + (size_t)(n0 + 256) * 3;
    const float* pB0 = preds + (size_t)(n0 + 512) * 3;
    const float* pB1 = preds + (size_t)(n0 + 768) * 3;
    const u64 pxA = pk(m2*pA0[0], m2*pA1[0]), pyA = pk(m2*pA0[1], m2*pA1[1]);
    const u64 pzA = pk(m2*pA0[2], m2*pA1[2]);
    const u64 pxB = pk(m2*pB0[0], m2*pB1[0]), pyB = pk(m2*pB0[1], m2*pB1[1]);
    const u64 pzB = pk(m2*pB0[2], m2*pB1[2]);
    const u64 wpA = pk(efl * g_pn[n0],       efl * g_pn[n0 + 256]);
    const u64 wpB = pk(efl * g_pn[n0 + 512], efl * g_pn[n0 + 768]);

    u64 rA = 0ull, oA = 0ull, rB = 0ull, oB = 0ull;
#pragma unroll 4
    for (int i = 0; i < CH; i++) {
        ulonglong2 A = sA[i];
        ulonglong2 Bv = sB[i];
        u64 g2 = sG[i];
        u64 argA = fma2(Bv.x, pzA, fma2(A.y, pyA, fma2(A.x, pxA, add2(Bv.y, wpA))));
        u64 argB = fma2(Bv.x, pzB, fma2(A.y, pyB, fma2(A.x, pxB, add2(Bv.y, wpB))));
        float a0, a1, b0, b1;
        upk(argA, a0, a1); upk(argB, b0, b1);
        if (SKIP) {
            float mx = fmaxf(fmaxf(a0, a1), fmaxf(b0, b1));
            if (__ballot_sync(0xFFFFFFFFu, mx > UTH) == 0u) continue;
        }
        u64 eA = pk(ex2f(a0), ex2f(a1));
        u64 eB = pk(ex2f(b0), ex2f(b1));
        u64 tA = mul2(eA, g2);
        u64 tB = mul2(eB, g2);
        rA = add2(rA, tA); oA = fma2(tA, argA, oA);   // o accumulates efl*t*d
        rB = add2(rB, tB); oB = fma2(tB, argB, oB);
    }
    float r0, r1, r2, r3, o0, o1, o2, o3;
    upk(rA, r0, r1); upk(rB, r2, r3);
    upk(oA, o0, o1); upk(oB, o2, o3);
    g_Rp[chunk][n0      ] = r0;
    g_Rp[chunk][n0 + 256] = r1;
    g_Rp[chunk][n0 + 512] = r2;
    g_Rp[chunk][n0 + 768] = r3;

    float c0 = g_curr[n0],       c1 = g_curr[n0 + 256];
    float c2v = g_curr[n0 + 512], c3 = g_curr[n0 + 768];
    float v = inv_efl * (c0*o0 + c1*o1 + c2v*o2 + c3*o3);
#pragma unroll
    for (int off = 16; off > 0; off >>= 1)
        v += __shfl_down_sync(0xFFFFFFFFu, v, off);
    if ((threadIdx.x & 31) == 0) sred[threadIdx.x >> 5] = v;
    __syncthreads();
    if (threadIdx.x == 0) {
        float s = 0.0f;
#pragma unroll
        for (int w = 0; w < 8; w++) s += sred[w];
        atomicAdd(&g_out, (double)s);
    }
}

__global__ void k_small2() {
    int idx = blockIdx.x * 256 + threadIdx.x;
    if (idx >= BN) return;
    float r = 0.0f;
#pragma unroll
    for (int ch = 0; ch < NCHUNK; ch++) r += g_Rp[ch][idx];
    float c = g_curr[idx];
    g_curr[idx] = fmaxf(c - c * r, 0.0f);
}

// Last step (ef==0): E==1 everywhere. Closed form, O(N) per batch.
__global__ void k_ef0(const float* __restrict__ preds,
                      const float* __restrict__ labels) {
    const int b = blockIdx.x;
    const int tid = threadIdx.x;
    __shared__ float red[256];

    float C = 0, CP = 0, CX = 0, CY = 0, CZ = 0;
    for (int n = tid; n < NN; n += 256) {
        float c = g_curr[b * NN + n];
        const float* p = preds + ((size_t)b * NN + n) * 3;
        C += c; CP += c * g_pn[b*NN+n];
        CX += c * p[0]; CY += c * p[1]; CZ += c * p[2];
    }
    auto reduce = [&](float v) -> float {
        red[tid] = v; __syncthreads();
        for (int s = 128; s > 0; s >>= 1) {
            if (tid < s) red[tid] += red[tid + s];
            __syncthreads();
        }
        float r = red[0]; __syncthreads();
        return r;
    };
    float Cs = reduce(C);
    float CPs = reduce(CP);
    float CXs = reduce(CX);
    float CYs = reduce(CY);
    float CZs = reduce(CZ);

    float G = 0, GL = 0, GX = 0, GY = 0, GZ = 0;
    for (int m = tid; m < NN; m += 256) {
        float cost = g_cost[b * NN + m];
        float s1 = cost * (float)NN;
        float s2 = cost * Cs / (s1 + EPSV);
        float wt = fminf(cost / (s2 + EPSV), 1.0f);
        float g = cost * wt / (s1 + EPSV);
        const float* l = labels + ((size_t)b * NN + m) * 3;
        G += g; GL += g * g_lm[b*NN+m];
        GX += g * l[0]; GY += g * l[1]; GZ += g * l[2];
    }
    float Gs = reduce(G);
    float GLs = reduce(GL);
    float GXs = reduce(GX);
    float GYs = reduce(GY);
    float GZs = reduce(GZ);

    if (tid == 0) {
        double ob = (double)CPs * Gs + (double)Cs * GLs
                  - 2.0 * ((double)CXs * GXs + (double)CYs * GYs + (double)CZs * GZs);
        atomicAdd(&g_out, ob);
    }
}

__global__ void k_write(float* out) {
    out[0] = (float)g_out;
}

extern "C" void kernel_launch(void* const* d_in, const int* in_sizes, int n_in,
                              void* d_out, int out_size) {
    const float* preds = (const float*)d_in[0];
    const float* labels = (const float*)d_in[1];
    float* out = (float*)d_out;

    static const float EF[9] = {
        -16384.0f, -4096.0f, -1024.0f, -256.0f, -64.0f,
        -16.0f, -4.0f, -1.0f, -0.25f
    };
    const float L2E = 1.4426950408889634f;

    k_init<<<BN / 256, 256>>>(preds, labels);

    dim3 grid(NCHUNK, 2, BB);
    for (int s = 0; s < 9; s++) {
        float efl = EF[s] * L2E;
        if (s < 4) {   // ef <= -256: most tiles fully underflow -> ballot skip
            k_colpass<true><<<grid, 256>>>(preds, labels, efl);
            k_small1<<<BN / 256, 256>>>();
            k_rowpass<true><<<grid, 256>>>(preds, labels, efl, 1.0f / efl);
            k_small2<<<BN / 256, 256>>>();
        } else {
            k_colpass<false><<<grid, 256>>>(preds, labels, efl);
            k_small1<<<BN / 256, 256>>>();
            k_rowpass<false><<<grid, 256>>>(preds, labels, efl, 1.0f / efl);
            k_small2<<<BN / 256, 256>>>();
        }
    }
    k_ef0<<<BB, 256>>>(preds, labels);   // ef = 0 step, closed form
    k_write<<<1, 1>>>(out);
}

// round 7
// speedup vs baseline: 1.2321x; 1.0332x over previous
#include <cuda_runtime.h>
#include <cuda_bf16.h>

// ApproxEMD: B=16, N=2048, D=3. Flash-style, fully fused: 2 kernels per step.
//  colpass (fused currency update): applies prev-step currency update from R
//    partials while filling smem; computes column sums S_E, S_EC as partials.
//  rowpass (fused g/cost update): computes g from S_E/S_EC partials while
//    filling smem; produces R partials + output contribution.
// State (curr/cost) is double-buffered by step parity; duplicate blocks write
// bit-identical values (benign). Register-tiled 4 outputs/thread, f32x2 math,
// warp-ballot underflow skip on ef<=-1024 steps (exact: exp2(x)==0, x<-150).

#define BB 16
#define NN 2048
#define BN (BB*NN)
#define EPSV 1e-9f
#define CH 128            // rows/cols per smem chunk
#define NCHUNK (NN/CH)    // 16

__device__ float g_curr2[2][BN];
__device__ float g_cost2[2][BN];
__device__ float g_pn[BN];   // |p_n|^2
__device__ float g_lm[BN];   // |l_m|^2
__device__ float g_SEp[NCHUNK][BN];
__device__ float g_SECp[NCHUNK][BN];
__device__ float g_Rp[NCHUNK][BN];
__device__ double g_out;

typedef unsigned long long u64;

__device__ __forceinline__ float ex2f(float x) {
    float r;
    asm("ex2.approx.f32 %0, %1;" : "=f"(r) : "f"(x));
    return r;
}
__device__ __forceinline__ u64 pk(float lo, float hi) {
    u64 d;
    asm("mov.b64 %0, {%1, %2};" : "=l"(d)
        : "r"(__float_as_uint(lo)), "r"(__float_as_uint(hi)));
    return d;
}
__device__ __forceinline__ void upk(u64 v, float& lo, float& hi) {
    unsigned a, b;
    asm("mov.b64 {%0, %1}, %2;" : "=r"(a), "=r"(b) : "l"(v));
    lo = __uint_as_float(a); hi = __uint_as_float(b);
}
__device__ __forceinline__ u64 fma2(u64 a, u64 b, u64 c) {
    u64 d;
    asm("fma.rn.f32x2 %0, %1, %2, %3;" : "=l"(d) : "l"(a), "l"(b), "l"(c));
    return d;
}
__device__ __forceinline__ u64 add2(u64 a, u64 b) {
    u64 d;
    asm("add.rn.f32x2 %0, %1, %2;" : "=l"(d) : "l"(a), "l"(b));
    return d;
}
__device__ __forceinline__ u64 mul2(u64 a, u64 b) {
    u64 d;
    asm("mul.rn.f32x2 %0, %1, %2;" : "=l"(d) : "l"(a), "l"(b));
    return d;
}

#define UTH (-150.0f)   // exp2(arg)==+0.0f for arg < -150 (even via denormals)

__global__ void k_init(const float* __restrict__ preds,
                       const float* __restrict__ labels) {
    int idx = blockIdx.x * 256 + threadIdx.x;
    if (idx >= BN) return;
    const float* p = preds + (size_t)idx * 3;
    const float* l = labels + (size_t)idx * 3;
    g_pn[idx] = p[0]*p[0] + p[1]*p[1] + p[2]*p[2];
    g_lm[idx] = l[0]*l[0] + l[1]*l[1] + l[2]*l[2];
    g_curr2[0][idx] = 1.0f;
    g_cost2[0][idx] = 1.0f;
#pragma unroll
    for (int ch = 0; ch < NCHUNK; ch++) g_Rp[ch][idx] = 0.0f;
    if (idx == 0) g_out = 0.0;
}

// colpass: fused currency update + column sums.
// grid (NCHUNK, 2, BB), block 256. par = s&1 (reads curr[par], writes curr[1-par]).
template <bool SKIP>
__global__ void __launch_bounds__(256, 2) k_colpass(
    const float* __restrict__ preds, const float* __restrict__ labels,
    float efl, int par) {
    const int b = blockIdx.z;
    const int chunk = blockIdx.x;
    __shared__ ulonglong2 sA[CH];  // (px2, py2)  broadcast-packed raw coords
    __shared__ ulonglong2 sB[CH];  // (pz2, wn2)  wn = efl*|p|^2
    __shared__ u64        sC[CH];  // (c, c)

    if (threadIdx.x < CH) {
        const int n = b * NN + chunk * CH + threadIdx.x;
        // fused small2: currency update from previous step's R partials
        float r = 0.0f;
#pragma unroll
        for (int ch = 0; ch < NCHUNK; ch++) r += g_Rp[ch][n];
        float cu = g_curr2[par][n];
        float c = fmaxf(cu - cu * r, 0.0f);
        g_curr2[1 - par][n] = c;     // duplicate identical write across y-blocks
        const float* p = preds + (size_t)n * 3;
        float wn = efl * g_pn[n];
        sA[threadIdx.x] = make_ulonglong2(pk(p[0], p[0]), pk(p[1], p[1]));
        sB[threadIdx.x] = make_ulonglong2(pk(p[2], p[2]), pk(wn, wn));
        sC[threadIdx.x] = pk(c, c);
    }
    __syncthreads();

    // owned columns: m0, m0+256 (pair A), m0+512, m0+768 (pair B)
    const int m0 = b * NN + blockIdx.y * 1024 + threadIdx.x;
    const float m2 = -2.0f * efl;
    const float* lA0 = labels + (size_t)m0 * 3;
    const float* lA1 = labels + (size_t)(m0 + 256) * 3;
    const float* lB0 = labels + (size_t)(m0 + 512) * 3;
    const float* lB1 = labels + (size_t)(m0 + 768) * 3;
    const u64 lxA = pk(m2*lA0[0], m2*lA1[0]), lyA = pk(m2*lA0[1], m2*lA1[1]);
    const u64 lzA = pk(m2*lA0[2], m2*lA1[2]);
    const u64 lxB = pk(m2*lB0[0], m2*lB1[0]), lyB = pk(m2*lB0[1], m2*lB1[1]);
    const u64 lzB = pk(m2*lB0[2], m2*lB1[2]);
    const u64 wbA = pk(efl * g_lm[m0],       efl * g_lm[m0 + 256]);
    const u64 wbB = pk(efl * g_lm[m0 + 512], efl * g_lm[m0 + 768]);

    u64 sEA = 0ull, sECA = 0ull, sEB = 0ull, sECB = 0ull;
#pragma unroll 4
    for (int i = 0; i < CH; i++) {
        ulonglong2 A = sA[i];
        ulonglong2 Bv = sB[i];
        u64 c2 = sC[i];
        u64 argA = fma2(Bv.x, lzA, fma2(A.y, lyA, fma2(A.x, lxA, add2(Bv.y, wbA))));
        u64 argB = fma2(Bv.x, lzB, fma2(A.y, lyB, fma2(A.x, lxB, add2(Bv.y, wbB))));
        float a0, a1, b0, b1;
        upk(argA, a0, a1); upk(argB, b0, b1);
        if (SKIP) {
            float mx = fmaxf(fmaxf(a0, a1), fmaxf(b0, b1));
            if (__ballot_sync(0xFFFFFFFFu, mx > UTH) == 0u) continue;
        }
        u64 eA = pk(ex2f(a0), ex2f(a1));
        u64 eB = pk(ex2f(b0), ex2f(b1));
        sEA = add2(sEA, eA); sECA = fma2(eA, c2, sECA);
        sEB = add2(sEB, eB); sECB = fma2(eB, c2, sECB);
    }
    float e0, e1, e2, e3, c0, c1, c2v, c3;
    upk(sEA, e0, e1); upk(sEB, e2, e3);
    upk(sECA, c0, c1); upk(sECB, c2v, c3);
    g_SEp [chunk][m0      ] = e0;
    g_SEp [chunk][m0 + 256] = e1;
    g_SEp [chunk][m0 + 512] = e2;
    g_SEp [chunk][m0 + 768] = e3;
    g_SECp[chunk][m0      ] = c0;
    g_SECp[chunk][m0 + 256] = c1;
    g_SECp[chunk][m0 + 512] = c2v;
    g_SECp[chunk][m0 + 768] = c3;
}

// rowpass: fused g/cost update + row sums + output accumulation.
// grid (NCHUNK, 2, BB), block 256.
template <bool SKIP>
__global__ void __launch_bounds__(256, 2) k_rowpass(
    const float* __restrict__ preds, const float* __restrict__ labels,
    float efl, float inv_efl, int par) {
    const int b = blockIdx.z;
    const int chunk = blockIdx.x;
    __shared__ ulonglong2 sA[CH];  // (lx2, ly2) broadcast-packed
    __shared__ ulonglong2 sB[CH];  // (lz2, wl2) wl = efl*|l|^2
    __shared__ u64        sG[CH];  // (g, g)
    __shared__ float      sred[8];

    if (threadIdx.x < CH) {
        const int m = b * NN + chunk * CH + threadIdx.x;
        // fused small1: g + cost update from this step's column partials
        float se = 0.0f, sec = 0.0f;
#pragma unroll
        for (int ch = 0; ch < NCHUNK; ch++) {
            se += g_SEp[ch][m];
            sec += g_SECp[ch][m];
        }
        float cost = g_cost2[par][m];
        float s1 = cost * se;
        float s2 = cost * sec / (s1 + EPSV);
        float wt = fminf(cost / (s2 + EPSV), 1.0f);
        float gv = cost * wt / (s1 + EPSV);
        g_cost2[1 - par][m] = fmaxf(cost - s2 * wt, 0.0f);  // dup identical write
        const float* l = labels + (size_t)m * 3;
        float wl = efl * g_lm[m];
        sA[threadIdx.x] = make_ulonglong2(pk(l[0], l[0]), pk(l[1], l[1]));
        sB[threadIdx.x] = make_ulonglong2(pk(l[2], l[2]), pk(wl, wl));
        sG[threadIdx.x] = pk(gv, gv);
    }
    __syncthreads();

    const int n0 = b * NN + blockIdx.y * 1024 + threadIdx.x;
    const float m2 = -2.0f * efl;
    const float* pA0 = preds + (size_t)n0 * 3;
    const float* pA1 = preds + (size_t)(n0 + 256) * 3;
    const float* pB0 = preds + (size_t)(n0 + 512) * 3;
    const float* pB1 = preds + (size_t)(n0 + 768) * 3;
    const u64 pxA = pk(m2*pA0[0], m2*pA1[0]), pyA = pk(m2*pA0[1], m2*pA1[1]);
    const u64 pzA = pk(m2*pA0[2], m2*pA1[2]);
    const u64 pxB = pk(m2*pB0[0], m2*pB1[0]), pyB = pk(m2*pB0[1], m2*pB1[1]);
    const u64 pzB = pk(m2*pB0[2], m2*pB1[2]);
    const u64 wpA = pk(efl * g_pn[n0],       efl * g_pn[n0 + 256]);
    const u64 wpB = pk(efl * g_pn[n0 + 512], efl * g_pn[n0 + 768]);

    u64 rA = 0ull, oA = 0ull, rB = 0ull, oB = 0ull;
#pragma unroll 4
    for (int i = 0; i < CH; i++) {
        ulonglong2 A = sA[i];
        ulonglong2 Bv = sB[i];
        u64 g2 = sG[i];
        u64 argA = fma2(Bv.x, pzA, fma2(A.y, pyA, fma2(A.x, pxA, add2(Bv.y, wpA))));
        u64 argB = fma2(Bv.x, pzB, fma2(A.y, pyB, fma2(A.x, pxB, add2(Bv.y, wpB))));
        float a0, a1, b0, b1;
        upk(argA, a0, a1); upk(argB, b0, b1);
        if (SKIP) {
            float mx = fmaxf(fmaxf(a0, a1), fmaxf(b0, b1));
            if (__ballot_sync(0xFFFFFFFFu, mx > UTH) == 0u) continue;
        }
        u64 eA = pk(ex2f(a0), ex2f(a1));
        u64 eB = pk(ex2f(b0), ex2f(b1));
        u64 tA = mul2(eA, g2);
        u64 tB = mul2(eB, g2);
        rA = add2(rA, tA); oA = fma2(tA, argA, oA);   // o accumulates efl*t*d
        rB = add2(rB, tB); oB = fma2(tB, argB, oB);
    }
    float r0, r1, r2, r3, o0, o1, o2, o3;
    upk(rA, r0, r1); upk(rB, r2, r3);
    upk(oA, o0, o1); upk(oB, o2, o3);
    g_Rp[chunk][n0      ] = r0;
    g_Rp[chunk][n0 + 256] = r1;
    g_Rp[chunk][n0 + 512] = r2;
    g_Rp[chunk][n0 + 768] = r3;

    const float* cu = g_curr2[1 - par];   // updated currency written by colpass
    float c0 = cu[n0],       c1 = cu[n0 + 256];
    float c2v = cu[n0 + 512], c3 = cu[n0 + 768];
    float v = inv_efl * (c0*o0 + c1*o1 + c2v*o2 + c3*o3);
#pragma unroll
    for (int off = 16; off > 0; off >>= 1)
        v += __shfl_down_sync(0xFFFFFFFFu, v, off);
    if ((threadIdx.x & 31) == 0) sred[threadIdx.x >> 5] = v;
    __syncthreads();
    if (threadIdx.x == 0) {
        float s = 0.0f;
#pragma unroll
        for (int w = 0; w < 8; w++) s += sred[w];
        atomicAdd(&g_out, (double)s);
    }
}

// Last step (ef==0): E==1 everywhere -> closed form O(N) per batch.
// Applies the step-8 currency update inline (parity buffer 1 holds c_used(8)).
__global__ void k_ef0(const float* __restrict__ preds,
                      const float* __restrict__ labels) {
    const int b = blockIdx.x;
    const int tid = threadIdx.x;
    __shared__ float red[256];

    float C = 0, CP = 0, CX = 0, CY = 0, CZ = 0;
    for (int n = tid; n < NN; n += 256) {
        int idx = b * NN + n;
        float r = 0.0f;
#pragma unroll
        for (int ch = 0; ch < NCHUNK; ch++) r += g_Rp[ch][idx];
        float cu = g_curr2[1][idx];
        float c = fmaxf(cu - cu * r, 0.0f);
        const float* p = preds + (size_t)idx * 3;
        C += c; CP += c * g_pn[idx];
        CX += c * p[0]; CY += c * p[1]; CZ += c * p[2];
    }
    auto reduce = [&](float v) -> float {
        red[tid] = v; __syncthreads();
        for (int s = 128; s > 0; s >>= 1) {
            if (tid < s) red[tid] += red[tid + s];
            __syncthreads();
        }
        float r = red[0]; __syncthreads();
        return r;
    };
    float Cs = reduce(C);
    float CPs = reduce(CP);
    float CXs = reduce(CX);
    float CYs = reduce(CY);
    float CZs = reduce(CZ);

    float G = 0, GL = 0, GX = 0, GY = 0, GZ = 0;
    for (int m = tid; m < NN; m += 256) {
        int idx = b * NN + m;
        float cost = g_cost2[1][idx];   // cost after step 8 (written by rowpass 8)
        float s1 = cost * (float)NN;
        float s2 = cost * Cs / (s1 + EPSV);
        float wt = fminf(cost / (s2 + EPSV), 1.0f);
        float g = cost * wt / (s1 + EPSV);
        const float* l = labels + (size_t)idx * 3;
        G += g; GL += g * g_lm[idx];
        GX += g * l[0]; GY += g * l[1]; GZ += g * l[2];
    }
    float Gs = reduce(G);
    float GLs = reduce(GL);
    float GXs = reduce(GX);
    float GYs = reduce(GY);
    float GZs = reduce(GZ);

    if (tid == 0) {
        double ob = (double)CPs * Gs + (double)Cs * GLs
                  - 2.0 * ((double)CXs * GXs + (double)CYs * GYs + (double)CZs * GZs);
        atomicAdd(&g_out, ob);
    }
}

__global__ void k_write(float* out) {
    out[0] = (float)g_out;
}

extern "C" void kernel_launch(void* const* d_in, const int* in_sizes, int n_in,
                              void* d_out, int out_size) {
    const float* preds = (const float*)d_in[0];
    const float* labels = (const float*)d_in[1];
    float* out = (float*)d_out;

    static const float EF[9] = {
        -16384.0f, -4096.0f, -1024.0f, -256.0f, -64.0f,
        -16.0f, -4.0f, -1.0f, -0.25f
    };
    const float L2E = 1.4426950408889634f;

    k_init<<<BN / 256, 256>>>(preds, labels);

    dim3 grid(NCHUNK, 2, BB);
    for (int s = 0; s < 9; s++) {
        float efl = EF[s] * L2E;
        int par = s & 1;
        if (s < 3) {   // ef <= -1024: high tile-underflow rate -> ballot skip
            k_colpass<true><<<grid, 256>>>(preds, labels, efl, par);
            k_rowpass<true><<<grid, 256>>>(preds, labels, efl, 1.0f / efl, par);
        } else {
            k_colpass<false><<<grid, 256>>>(preds, labels, efl, par);
            k_rowpass<false><<<grid, 256>>>(preds, labels, efl, 1.0f / efl, par);
        }
    }
    k_ef0<<<BB, 256>>>(preds, labels);   // ef = 0 step, closed form
    k_write<<<1, 1>>>(out);
}

// round 8
// speedup vs baseline: 1.3443x; 1.0910x over previous
#include <cuda_runtime.h>
#include <cuda_bf16.h>

// ApproxEMD: B=16, N=2048, D=3. Flash-style, fused: 2 kernels per step.
//  colpass (fused currency update from prev R partials) -> S_E, S_EC partials
//  rowpass (fused g/cost update from S partials) -> R partials + out contrib
// State double-buffered by parity; duplicate identical writes are benign.
// 128-thread blocks, 1024-block grid for occupancy; 4 outputs/thread; f32x2
// packed math; warp-ballot underflow skip on ef<=-1024 (exp2(x)==0 for x<-150,
// exactly matching the fp32 reference underflow).

#define BB 16
#define NN 2048
#define BN (BB*NN)
#define EPSV 1e-9f
#define CH 128            // rows/cols per smem chunk
#define NCHUNK (NN/CH)    // 16
#define TPB 128

__device__ float g_curr2[2][BN];
__device__ float g_cost2[2][BN];
__device__ float g_pn[BN];   // |p_n|^2
__device__ float g_lm[BN];   // |l_m|^2
__device__ float g_SEp[NCHUNK][BN];
__device__ float g_SECp[NCHUNK][BN];
__device__ float g_Rp[NCHUNK][BN];
__device__ double g_out;

typedef unsigned long long u64;

__device__ __forceinline__ float ex2f(float x) {
    float r;
    asm("ex2.approx.f32 %0, %1;" : "=f"(r) : "f"(x));
    return r;
}
__device__ __forceinline__ u64 pk(float lo, float hi) {
    u64 d;
    asm("mov.b64 %0, {%1, %2};" : "=l"(d)
        : "r"(__float_as_uint(lo)), "r"(__float_as_uint(hi)));
    return d;
}
__device__ __forceinline__ void upk(u64 v, float& lo, float& hi) {
    unsigned a, b;
    asm("mov.b64 {%0, %1}, %2;" : "=r"(a), "=r"(b) : "l"(v));
    lo = __uint_as_float(a); hi = __uint_as_float(b);
}
__device__ __forceinline__ u64 fma2(u64 a, u64 b, u64 c) {
    u64 d;
    asm("fma.rn.f32x2 %0, %1, %2, %3;" : "=l"(d) : "l"(a), "l"(b), "l"(c));
    return d;
}
__device__ __forceinline__ u64 add2(u64 a, u64 b) {
    u64 d;
    asm("add.rn.f32x2 %0, %1, %2;" : "=l"(d) : "l"(a), "l"(b));
    return d;
}
__device__ __forceinline__ u64 mul2(u64 a, u64 b) {
    u64 d;
    asm("mul.rn.f32x2 %0, %1, %2;" : "=l"(d) : "l"(a), "l"(b));
    return d;
}

#define UTH (-150.0f)   // exp2(arg)==+0.0f for arg < -150 (even via denormals)

__global__ void k_init(const float* __restrict__ preds,
                       const float* __restrict__ labels) {
    int idx = blockIdx.x * 256 + threadIdx.x;
    if (idx >= BN) return;
    const float* p = preds + (size_t)idx * 3;
    const float* l = labels + (size_t)idx * 3;
    g_pn[idx] = p[0]*p[0] + p[1]*p[1] + p[2]*p[2];
    g_lm[idx] = l[0]*l[0] + l[1]*l[1] + l[2]*l[2];
    g_curr2[0][idx] = 1.0f;
    g_cost2[0][idx] = 1.0f;
#pragma unroll
    for (int ch = 0; ch < NCHUNK; ch++) g_Rp[ch][idx] = 0.0f;
    if (idx == 0) g_out = 0.0;
}

// colpass: fused currency update + column sums.
// grid (NCHUNK, 4, BB), block 128. par = s&1.
template <bool SKIP>
__global__ void __launch_bounds__(TPB) k_colpass(
    const float* __restrict__ preds, const float* __restrict__ labels,
    float efl, int par) {
    const int b = blockIdx.z;
    const int chunk = blockIdx.x;
    __shared__ ulonglong2 sA[CH];  // (px2, py2)  broadcast-packed raw coords
    __shared__ ulonglong2 sB[CH];  // (pz2, wn2)  wn = efl*|p|^2
    __shared__ u64        sC[CH];  // (c, c)

    {
        const int n = b * NN + chunk * CH + threadIdx.x;
        // fused small2: currency update from previous step's R partials
        float r = 0.0f;
#pragma unroll
        for (int ch = 0; ch < NCHUNK; ch++) r += g_Rp[ch][n];
        float cu = g_curr2[par][n];
        float c = fmaxf(cu - cu * r, 0.0f);
        g_curr2[1 - par][n] = c;     // duplicate identical write across y-blocks
        const float* p = preds + (size_t)n * 3;
        float wn = efl * g_pn[n];
        sA[threadIdx.x] = make_ulonglong2(pk(p[0], p[0]), pk(p[1], p[1]));
        sB[threadIdx.x] = make_ulonglong2(pk(p[2], p[2]), pk(wn, wn));
        sC[threadIdx.x] = pk(c, c);
    }
    __syncthreads();

    // owned columns: m0, m0+128 (pair A), m0+256, m0+384 (pair B)
    const int m0 = b * NN + blockIdx.y * 512 + threadIdx.x;
    const float m2 = -2.0f * efl;
    const float* lA0 = labels + (size_t)m0 * 3;
    const float* lA1 = labels + (size_t)(m0 + 128) * 3;
    const float* lB0 = labels + (size_t)(m0 + 256) * 3;
    const float* lB1 = labels + (size_t)(m0 + 384) * 3;
    const u64 lxA = pk(m2*lA0[0], m2*lA1[0]), lyA = pk(m2*lA0[1], m2*lA1[1]);
    const u64 lzA = pk(m2*lA0[2], m2*lA1[2]);
    const u64 lxB = pk(m2*lB0[0], m2*lB1[0]), lyB = pk(m2*lB0[1], m2*lB1[1]);
    const u64 lzB = pk(m2*lB0[2], m2*lB1[2]);
    const u64 wbA = pk(efl * g_lm[m0],       efl * g_lm[m0 + 128]);
    const u64 wbB = pk(efl * g_lm[m0 + 256], efl * g_lm[m0 + 384]);

    u64 sEA = 0ull, sECA = 0ull, sEB = 0ull, sECB = 0ull;
#pragma unroll 8
    for (int i = 0; i < CH; i++) {
        ulonglong2 A = sA[i];
        ulonglong2 Bv = sB[i];
        u64 c2 = sC[i];
        u64 argA = fma2(Bv.x, lzA, fma2(A.y, lyA, fma2(A.x, lxA, add2(Bv.y, wbA))));
        u64 argB = fma2(Bv.x, lzB, fma2(A.y, lyB, fma2(A.x, lxB, add2(Bv.y, wbB))));
        float a0, a1, b0, b1;
        upk(argA, a0, a1); upk(argB, b0, b1);
        if (SKIP) {
            float mx = fmaxf(fmaxf(a0, a1), fmaxf(b0, b1));
            if (__ballot_sync(0xFFFFFFFFu, mx > UTH) == 0u) continue;
        }
        u64 eA = pk(ex2f(a0), ex2f(a1));
        u64 eB = pk(ex2f(b0), ex2f(b1));
        sEA = add2(sEA, eA); sECA = fma2(eA, c2, sECA);
        sEB = add2(sEB, eB); sECB = fma2(eB, c2, sECB);
    }
    float e0, e1, e2, e3, c0, c1, c2v, c3;
    upk(sEA, e0, e1); upk(sEB, e2, e3);
    upk(sECA, c0, c1); upk(sECB, c2v, c3);
    g_SEp [chunk][m0      ] = e0;
    g_SEp [chunk][m0 + 128] = e1;
    g_SEp [chunk][m0 + 256] = e2;
    g_SEp [chunk][m0 + 384] = e3;
    g_SECp[chunk][m0      ] = c0;
    g_SECp[chunk][m0 + 128] = c1;
    g_SECp[chunk][m0 + 256] = c2v;
    g_SECp[chunk][m0 + 384] = c3;
}

// rowpass: fused g/cost update + row sums + output accumulation.
// grid (NCHUNK, 4, BB), block 128.
template <bool SKIP>
__global__ void __launch_bounds__(TPB) k_rowpass(
    const float* __restrict__ preds, const float* __restrict__ labels,
    float efl, float inv_efl, int par) {
    const int b = blockIdx.z;
    const int chunk = blockIdx.x;
    __shared__ ulonglong2 sA[CH];  // (lx2, ly2) broadcast-packed
    __shared__ ulonglong2 sB[CH];  // (lz2, wl2) wl = efl*|l|^2
    __shared__ u64        sG[CH];  // (g, g)
    __shared__ float      sred[4];

    {
        const int m = b * NN + chunk * CH + threadIdx.x;
        // fused small1: g + cost update from this step's column partials
        float se = 0.0f, sec = 0.0f;
#pragma unroll
        for (int ch = 0; ch < NCHUNK; ch++) {
            se += g_SEp[ch][m];
            sec += g_SECp[ch][m];
        }
        float cost = g_cost2[par][m];
        float s1 = cost * se;
        float s2 = cost * sec / (s1 + EPSV);
        float wt = fminf(cost / (s2 + EPSV), 1.0f);
        float gv = cost * wt / (s1 + EPSV);
        g_cost2[1 - par][m] = fmaxf(cost - s2 * wt, 0.0f);  // dup identical write
        const float* l = labels + (size_t)m * 3;
        float wl = efl * g_lm[m];
        sA[threadIdx.x] = make_ulonglong2(pk(l[0], l[0]), pk(l[1], l[1]));
        sB[threadIdx.x] = make_ulonglong2(pk(l[2], l[2]), pk(wl, wl));
        sG[threadIdx.x] = pk(gv, gv);
    }
    __syncthreads();

    const int n0 = b * NN + blockIdx.y * 512 + threadIdx.x;
    const float m2 = -2.0f * efl;
    const float* pA0 = preds + (size_t)n0 * 3;
    const float* pA1 = preds + (size_t)(n0 + 128) * 3;
    const float* pB0 = preds + (size_t)(n0 + 256) * 3;
    const float* pB1 = preds + (size_t)(n0 + 384) * 3;
    const u64 pxA = pk(m2*pA0[0], m2*pA1[0]), pyA = pk(m2*pA0[1], m2*pA1[1]);
    const u64 pzA = pk(m2*pA0[2], m2*pA1[2]);
    const u64 pxB = pk(m2*pB0[0], m2*pB1[0]), pyB = pk(m2*pB0[1], m2*pB1[1]);
    const u64 pzB = pk(m2*pB0[2], m2*pB1[2]);
    const u64 wpA = pk(efl * g_pn[n0],       efl * g_pn[n0 + 128]);
    const u64 wpB = pk(efl * g_pn[n0 + 256], efl * g_pn[n0 + 384]);

    // prefetch updated currency (written by this step's colpass)
    const float* cu = g_curr2[1 - par];
    const float c0 = cu[n0],        c1 = cu[n0 + 128];
    const float c2v = cu[n0 + 256], c3 = cu[n0 + 384];

    u64 rA = 0ull, oA = 0ull, rB = 0ull, oB = 0ull;
#pragma unroll 8
    for (int i = 0; i < CH; i++) {
        ulonglong2 A = sA[i];
        ulonglong2 Bv = sB[i];
        u64 g2 = sG[i];
        u64 argA = fma2(Bv.x, pzA, fma2(A.y, pyA, fma2(A.x, pxA, add2(Bv.y, wpA))));
        u64 argB = fma2(Bv.x, pzB, fma2(A.y, pyB, fma2(A.x, pxB, add2(Bv.y, wpB))));
        float a0, a1, b0, b1;
        upk(argA, a0, a1); upk(argB, b0, b1);
        if (SKIP) {
            float mx = fmaxf(fmaxf(a0, a1), fmaxf(b0, b1));
            if (__ballot_sync(0xFFFFFFFFu, mx > UTH) == 0u) continue;
        }
        u64 eA = pk(ex2f(a0), ex2f(a1));
        u64 eB = pk(ex2f(b0), ex2f(b1));
        u64 tA = mul2(eA, g2);
        u64 tB = mul2(eB, g2);
        rA = add2(rA, tA); oA = fma2(tA, argA, oA);   // o accumulates efl*t*d
        rB = add2(rB, tB); oB = fma2(tB, argB, oB);
    }
    float r0, r1, r2, r3, o0, o1, o2, o3;
    upk(rA, r0, r1); upk(rB, r2, r3);
    upk(oA, o0, o1); upk(oB, o2, o3);
    g_Rp[chunk][n0      ] = r0;
    g_Rp[chunk][n0 + 128] = r1;
    g_Rp[chunk][n0 + 256] = r2;
    g_Rp[chunk][n0 + 384] = r3;

    float v = inv_efl * (c0*o0 + c1*o1 + c2v*o2 + c3*o3);
#pragma unroll
    for (int off = 16; off > 0; off >>= 1)
        v += __shfl_down_sync(0xFFFFFFFFu, v, off);
    if ((threadIdx.x & 31) == 0) sred[threadIdx.x >> 5] = v;
    __syncthreads();
    if (threadIdx.x == 0) {
        float s = sred[0] + sred[1] + sred[2] + sred[3];
        atomicAdd(&g_out, (double)s);
    }
}

// Last step (ef==0): E==1 everywhere -> closed form O(N) per batch.
__global__ void k_ef0(const float* __restrict__ preds,
                      const float* __restrict__ labels) {
    const int b = blockIdx.x;
    const int tid = threadIdx.x;
    __shared__ float red[256];

    float C = 0, CP = 0, CX = 0, CY = 0, CZ = 0;
    for (int n = tid; n < NN; n += 256) {
        int idx = b * NN + n;
        float r = 0.0f;
#pragma unroll
        for (int ch = 0; ch < NCHUNK; ch++) r += g_Rp[ch][idx];
        float cu = g_curr2[1][idx];
        float c = fmaxf(cu - cu * r, 0.0f);
        const float* p = preds + (size_t)idx * 3;
        C += c; CP += c * g_pn[idx];
        CX += c * p[0]; CY += c * p[1]; CZ += c * p[2];
    }
    auto reduce = [&](float v) -> float {
        red[tid] = v; __syncthreads();
        for (int s = 128; s > 0; s >>= 1) {
            if (tid < s) red[tid] += red[tid + s];
            __syncthreads();
        }
        float r = red[0]; __syncthreads();
        return r;
    };
    float Cs = reduce(C);
    float CPs = reduce(CP);
    float CXs = reduce(CX);
    float CYs = reduce(CY);
    float CZs = reduce(CZ);

    float G = 0, GL = 0, GX = 0, GY = 0, GZ = 0;
    for (int m = tid; m < NN; m += 256) {
        int idx = b * NN + m;
        float cost = g_cost2[1][idx];   // cost after step 8
        float s1 = cost * (float)NN;
        float s2 = cost * Cs / (s1 + EPSV);
        float wt = fminf(cost / (s2 + EPSV), 1.0f);
        float g = cost * wt / (s1 + EPSV);
        const float* l = labels + (size_t)idx * 3;
        G += g; GL += g * g_lm[idx];
        GX += g * l[0]; GY += g * l[1]; GZ += g * l[2];
    }
    float Gs = reduce(G);
    float GLs = reduce(GL);
    float GXs = reduce(GX);
    float GYs = reduce(GY);
    float GZs = reduce(GZ);

    if (tid == 0) {
        double ob = (double)CPs * Gs + (double)Cs * GLs
                  - 2.0 * ((double)CXs * GXs + (double)CYs * GYs + (double)CZs * GZs);
        atomicAdd(&g_out, ob);
    }
}

__global__ void k_write(float* out) {
    out[0] = (float)g_out;
}

extern "C" void kernel_launch(void* const* d_in, const int* in_sizes, int n_in,
                              void* d_out, int out_size) {
    const float* preds = (const float*)d_in[0];
    const float* labels = (const float*)d_in[1];
    float* out = (float*)d_out;

    static const float EF[9] = {
        -16384.0f, -4096.0f, -1024.0f, -256.0f, -64.0f,
        -16.0f, -4.0f, -1.0f, -0.25f
    };
    const float L2E = 1.4426950408889634f;

    k_init<<<BN / 256, 256>>>(preds, labels);

    dim3 grid(NCHUNK, 4, BB);   // 1024 blocks of 128 threads
    for (int s = 0; s < 9; s++) {
        float efl = EF[s] * L2E;
        int par = s & 1;
        if (s < 3) {   // ef <= -1024: high tile-underflow rate -> ballot skip
            k_colpass<true><<<grid, TPB>>>(preds, labels, efl, par);
            k_rowpass<true><<<grid, TPB>>>(preds, labels, efl, 1.0f / efl, par);
        } else {
            k_colpass<false><<<grid, TPB>>>(preds, labels, efl, par);
            k_rowpass<false><<<grid, TPB>>>(preds, labels, efl, 1.0f / efl, par);
        }
    }
    k_ef0<<<BB, 256>>>(preds, labels);   // ef = 0 step, closed form
    k_write<<<1, 1>>>(out);
}